// round 12
// baseline (speedup 1.0000x reference)
#include <cuda_runtime.h>
#include <cuda_bf16.h>
#include <cstdint>

// ---------------- Problem constants ----------------
#define NNODES 50000
#define NEDGES 800000
#define ETOT   (NEDGES + NNODES)   // + self loops
#define NBLK   ((NNODES + 1023) / 1024)   // 49 scan blocks
#define NT16   (NNODES / 16)              // 3125 16-row fragment tiles (exact)

typedef unsigned long long u64;

// W fragment buffer layout (u64 units):
//   L1: [0, 16384)   4 parts x 4096 (COLS=128, PART=8*16*32)
//   L2: [16384, 32768)
//   L3: [32768, 40960) 4 parts x 2048 (COLS=64)
#define WF_L1 0
#define WF_L2 16384
#define WF_L3 32768

// ---------------- Device scratch (no allocs allowed) ----------------
__device__ float g_xl[NNODES * 128];
__device__ float g_xr[NNODES * 128];
__device__ uint4 g_xfh[NT16 * 8 * 32];   // A-fragments hi [tile16][ks][lane]
__device__ uint4 g_xfl[NT16 * 8 * 32];   // A-fragments lo
__device__ u64   g_wf[40960];            // all layers' W B-fragments
__device__ int   g_src[ETOT];
__device__ int   g_dst[ETOT];
__device__ int   g_csrc[ETOT];           // src ids sorted by dst (CSR)
__device__ int   g_rowptr[NNODES + 1];
__device__ int   g_deg[NNODES];
__device__ int   g_cnt[NNODES];
__device__ int   g_bsum[NBLK];
__device__ int   g_boff[NBLK];
__device__ int   g_is64;

// ---------------- mma.sync bf16 (sm_80+ PTX, family-wide) ----------------
__device__ __forceinline__ void mma_bf16(float* c, const uint4& a, u64 b) {
    unsigned b0 = (unsigned)b, b1 = (unsigned)(b >> 32);
    asm volatile(
        "mma.sync.aligned.m16n8k16.row.col.f32.bf16.bf16.f32 "
        "{%0,%1,%2,%3}, {%4,%5,%6,%7}, {%8,%9}, {%0,%1,%2,%3};"
        : "+f"(c[0]), "+f"(c[1]), "+f"(c[2]), "+f"(c[3])
        : "r"(a.x), "r"(a.y), "r"(a.z), "r"(a.w), "r"(b0), "r"(b1));
}

__device__ __forceinline__ unsigned pack_hi(float x, float y,
                                            unsigned& lo_out) {
    __nv_bfloat16 hx = __float2bfloat16_rn(x);
    __nv_bfloat16 hy = __float2bfloat16_rn(y);
    __nv_bfloat16 lx = __float2bfloat16_rn(x - __bfloat162float(hx));
    __nv_bfloat16 ly = __float2bfloat16_rn(y - __bfloat162float(hy));
    lo_out = ((unsigned)__bfloat16_as_ushort(ly) << 16) | __bfloat16_as_ushort(lx);
    return ((unsigned)__bfloat16_as_ushort(hy) << 16) | __bfloat16_as_ushort(hx);
}

// ---------------- zero counters + parallel dtype detect ----------------
__global__ void prep_kernel(const int* ei) {
    int i = blockIdx.x * blockDim.x + threadIdx.x;
    if (i < NNODES) { g_deg[i] = 0; g_cnt[i] = 0; }
    if (blockIdx.x == 0 && threadIdx.x < 32) {
        int nz = 0;
#pragma unroll
        for (int q = 0; q < 4; q++)
            nz |= ei[2 * (threadIdx.x * 4 + q) + 1];
        unsigned any = __ballot_sync(0xffffffffu, nz != 0);
        if (threadIdx.x == 0) g_is64 = (any == 0u);
    }
}

__global__ void canon_hist_kernel(const void* ei) {
    int i = blockIdx.x * blockDim.x + threadIdx.x;
    if (i >= ETOT) return;
    int s, d;
    if (i < NEDGES) {
        if (g_is64) {
            const long long* p = (const long long*)ei;
            s = (int)p[i];
            d = (int)p[NEDGES + i];
        } else {
            const int* p = (const int*)ei;
            s = p[i];
            d = p[NEDGES + i];
        }
    } else {
        s = d = i - NEDGES;
    }
    g_src[i] = s;
    g_dst[i] = d;
    atomicAdd(&g_deg[d], 1);
}

__global__ void scan1_kernel() {
    __shared__ int wtot[32];
    const int t = threadIdx.x, lane = t & 31, wid = t >> 5;
    const int gi = blockIdx.x * 1024 + t;
    int v = (gi < NNODES) ? g_deg[gi] : 0;
    int incl = v;
#pragma unroll
    for (int off = 1; off < 32; off <<= 1) {
        int x = __shfl_up_sync(0xffffffffu, incl, off);
        if (lane >= off) incl += x;
    }
    if (lane == 31) wtot[wid] = incl;
    __syncthreads();
    if (wid == 0) {
        int wv = wtot[lane];
        int wi = wv;
#pragma unroll
        for (int off = 1; off < 32; off <<= 1) {
            int x = __shfl_up_sync(0xffffffffu, wi, off);
            if (lane >= off) wi += x;
        }
        wtot[lane] = wi - wv;
    }
    __syncthreads();
    int excl = wtot[wid] + incl - v;
    if (gi < NNODES) g_rowptr[gi] = excl;
    if (t == 1023) g_bsum[blockIdx.x] = excl + v;
}

__global__ void scan2_kernel() {
    if (threadIdx.x == 0) {
        int t = 0;
#pragma unroll
        for (int ib = 0; ib < NBLK; ib++) {
            int v = g_bsum[ib];
            g_boff[ib] = t;
            t += v;
        }
        g_rowptr[NNODES] = t;
    }
}

__global__ void scan3_kernel() {
    int gi = blockIdx.x * 1024 + threadIdx.x;
    if (gi < NNODES && blockIdx.x > 0) g_rowptr[gi] += g_boff[blockIdx.x];
}

__global__ void scatter_kernel() {
    int i = blockIdx.x * blockDim.x + threadIdx.x;
    if (i >= ETOT) return;
    int d = g_dst[i];
    int pos = g_rowptr[d] + atomicAdd(&g_cnt[d], 1);
    g_csrc[pos] = g_src[i];
}

// ---------------- X -> A-fragment-major hi/lo conversion (layer 1 only) ----
__global__ void convert_x_kernel(const float* __restrict__ act) {
    int idx = blockIdx.x * blockDim.x + threadIdx.x;
    if (idx >= NT16 * 8 * 32) return;
    int lane = idx & 31;
    int ks = (idx >> 5) & 7;
    int tile = idx >> 8;
    int g = lane >> 2, t = lane & 3;
    int r0 = tile * 16 + g, r1 = r0 + 8;
    int c0 = (ks * 8 + t) * 2;
    int c1 = c0 + 8;

    float2 v0 = *(const float2*)&act[r0 * 128 + c0];
    float2 v1 = *(const float2*)&act[r1 * 128 + c0];
    float2 v2 = *(const float2*)&act[r0 * 128 + c1];
    float2 v3 = *(const float2*)&act[r1 * 128 + c1];

    uint4 hi, lo;
    hi.x = pack_hi(v0.x, v0.y, lo.x);
    hi.y = pack_hi(v1.x, v1.y, lo.y);
    hi.z = pack_hi(v2.x, v2.y, lo.z);
    hi.w = pack_hi(v3.x, v3.y, lo.w);
    g_xfh[idx] = hi;
    g_xfl[idx] = lo;
}

// ---------------- All-layer W -> B-fragment conversion (one kernel) --------
__device__ __forceinline__ void convert_w_one(u64* base, const float* Wl,
                                              const float* Wr, int local,
                                              int COLS, int NT, int PART) {
    int lane = local & 31;
    int nt = (local >> 5) % NT;
    int ks = (local >> 5) / NT;
    int g = lane >> 2, t = lane & 3;
    int n = nt * 8 + g;
    int k0 = (ks * 8 + t) * 2;
    int k1 = k0 + 8;

    unsigned lo0, lo1;
    unsigned hi0 = pack_hi(Wl[k0 * COLS + n], Wl[(k0 + 1) * COLS + n], lo0);
    unsigned hi1 = pack_hi(Wl[k1 * COLS + n], Wl[(k1 + 1) * COLS + n], lo1);
    base[0 * PART + local] = ((u64)hi1 << 32) | hi0;
    base[1 * PART + local] = ((u64)lo1 << 32) | lo0;

    hi0 = pack_hi(Wr[k0 * COLS + n], Wr[(k0 + 1) * COLS + n], lo0);
    hi1 = pack_hi(Wr[k1 * COLS + n], Wr[(k1 + 1) * COLS + n], lo1);
    base[2 * PART + local] = ((u64)hi1 << 32) | hi0;
    base[3 * PART + local] = ((u64)lo1 << 32) | lo0;
}

__global__ void convert_w_all_kernel(const float* W1l, const float* W1r,
                                     const float* W2l, const float* W2r,
                                     const float* W3l, const float* W3r) {
    int idx = blockIdx.x * blockDim.x + threadIdx.x;
    if (idx < 4096) {
        convert_w_one(g_wf + WF_L1, W1l, W1r, idx, 128, 16, 4096);
    } else if (idx < 8192) {
        convert_w_one(g_wf + WF_L2, W2l, W2r, idx - 4096, 128, 16, 4096);
    } else if (idx < 10240) {
        convert_w_one(g_wf + WF_L3, W3l, W3r, idx - 8192, 64, 8, 2048);
    }
}

// ---------------- HMMA dual GEMM (fragment-major, per-matrix CTA) ----------
// 3xBF16 split: D = Xhi@Whi + Xhi@Wlo + Xlo@Whi, fp32 accumulate.
// blockIdx.y selects matrix (0 -> Yl, 1 -> Yr); 8 warps = 8 row tiles.
template <int COLS>
__global__ __launch_bounds__(256) void gemm_mma_kernel(const u64* __restrict__ wf,
                                                       float* __restrict__ Yl,
                                                       float* __restrict__ Yr) {
    constexpr int NT = COLS / 8;
    constexpr int PART = 8 * NT * 32;
    const int tid = threadIdx.x;
    const int w = tid >> 5, lane = tid & 31;
    const int mat = blockIdx.y;
    const int tile = blockIdx.x * 8 + w;
    if (tile >= NT16) return;
    const int g = lane >> 2, t = lane & 3;

    const u64* Wh = wf + mat * 2 * PART;
    const u64* Wlo = Wh + PART;
    const uint4* Ah = g_xfh + tile * 256;
    const uint4* Al = g_xfl + tile * 256;

    float acc[NT][4];
#pragma unroll
    for (int nt = 0; nt < NT; nt++)
#pragma unroll
        for (int j = 0; j < 4; j++) acc[nt][j] = 0.0f;

#pragma unroll
    for (int ks = 0; ks < 8; ks++) {
        uint4 ahi = Ah[ks * 32 + lane];
        uint4 alo = Al[ks * 32 + lane];
        const u64* whk = Wh + (ks * NT) * 32 + lane;
        const u64* wlk = Wlo + (ks * NT) * 32 + lane;
#pragma unroll
        for (int nt = 0; nt < NT; nt++) {
            u64 bh = whk[nt * 32];
            u64 bl = wlk[nt * 32];
            mma_bf16(acc[nt], ahi, bh);
            mma_bf16(acc[nt], ahi, bl);
            mma_bf16(acc[nt], alo, bh);
        }
    }

    float* Y = mat ? Yr : Yl;
    const int r0 = tile * 16 + g, r1 = r0 + 8;
#pragma unroll
    for (int nt = 0; nt < NT; nt++) {
        int c = nt * 8 + t * 2;
        *(float2*)&Y[r0 * COLS + c] = make_float2(acc[nt][0], acc[nt][1]);
        *(float2*)&Y[r1 * COLS + c] = make_float2(acc[nt][2], acc[nt][3]);
    }
}

// ---------------- CSR edge pass: 2-edge pipelined, optional fused convert ---
// FUSE=true (128-col layers feeding another layer): write next layer's
// A-fragments (split bf16 hi/lo) directly from registers; no fp32 output.
template <int ROWF4, bool FUSE>
__global__ void csr_edge_kernel(const float* __restrict__ att,
                                const float* __restrict__ bias,
                                float* __restrict__ out) {
    constexpr int NPW = 32 / ROWF4;
    int gwarp = (blockIdx.x * blockDim.x + threadIdx.x) >> 5;
    int lane = threadIdx.x & 31;
    int sub = lane / ROWF4;
    int l = lane % ROWF4;
    int d = gwarp * NPW + sub;
    if (d >= NNODES) return;

    const float4* xl4 = (const float4*)g_xl;
    float4 b = ((const float4*)g_xr)[d * ROWF4 + l];
    float4 w = ((const float4*)att)[l];

    float4 acc = make_float4(0.f, 0.f, 0.f, 0.f);
    float den = 0.f;

    int i = g_rowptr[d];
    const int end = g_rowptr[d + 1];

    int s0 = g_csrc[i];
    int s1 = (i + 1 < end) ? g_csrc[i + 1] : 0;
    float4 a0 = xl4[s0 * ROWF4 + l];
    float4 a1 = xl4[s1 * ROWF4 + l];

    while (i < end) {
        const int ni = i + 2;
        int t0 = (ni < end) ? g_csrc[ni] : 0;
        int t1 = (ni + 1 < end) ? g_csrc[ni + 1] : 0;
        float4 n0 = xl4[t0 * ROWF4 + l];
        float4 n1 = xl4[t1 * ROWF4 + l];

        float vx0 = a0.x + b.x, vy0 = a0.y + b.y, vz0 = a0.z + b.z, vw0 = a0.w + b.w;
        float vx1 = a1.x + b.x, vy1 = a1.y + b.y, vz1 = a1.z + b.z, vw1 = a1.w + b.w;
        vx0 = vx0 > 0.f ? vx0 : 0.2f * vx0;  vx1 = vx1 > 0.f ? vx1 : 0.2f * vx1;
        vy0 = vy0 > 0.f ? vy0 : 0.2f * vy0;  vy1 = vy1 > 0.f ? vy1 : 0.2f * vy1;
        vz0 = vz0 > 0.f ? vz0 : 0.2f * vz0;  vz1 = vz1 > 0.f ? vz1 : 0.2f * vz1;
        vw0 = vw0 > 0.f ? vw0 : 0.2f * vw0;  vw1 = vw1 > 0.f ? vw1 : 0.2f * vw1;
        float p0 = vx0 * w.x + vy0 * w.y + vz0 * w.z + vw0 * w.w;
        float p1 = vx1 * w.x + vy1 * w.y + vz1 * w.z + vw1 * w.w;

        p0 += __shfl_xor_sync(0xffffffffu, p0, 8);
        p1 += __shfl_xor_sync(0xffffffffu, p1, 8);
        p0 += __shfl_xor_sync(0xffffffffu, p0, 4);
        p1 += __shfl_xor_sync(0xffffffffu, p1, 4);
        p0 += __shfl_xor_sync(0xffffffffu, p0, 2);
        p1 += __shfl_xor_sync(0xffffffffu, p1, 2);
        p0 += __shfl_xor_sync(0xffffffffu, p0, 1);
        p1 += __shfl_xor_sync(0xffffffffu, p1, 1);

        float ex0 = __expf(p0);
        float ex1 = (i + 1 < end) ? __expf(p1) : 0.f;

        acc.x += ex0 * a0.x + ex1 * a1.x;
        acc.y += ex0 * a0.y + ex1 * a1.y;
        acc.z += ex0 * a0.z + ex1 * a1.z;
        acc.w += ex0 * a0.w + ex1 * a1.w;
        den += ex0 + ex1;

        a0 = n0; a1 = n1;
        i = ni;
    }

    float4 bi = ((const float4*)bias)[l];
    float inv = 1.0f / den;
    float4 o;
    o.x = acc.x * inv + bi.x;
    o.y = acc.y * inv + bi.y;
    o.z = acc.z * inv + bi.z;
    o.w = acc.w * inv + bi.w;
    o.x = o.x > 0.f ? o.x : (__expf(o.x) - 1.f);
    o.y = o.y > 0.f ? o.y : (__expf(o.y) - 1.f);
    o.z = o.z > 0.f ? o.z : (__expf(o.z) - 1.f);
    o.w = o.w > 0.f ? o.w : (__expf(o.w) - 1.f);

    if (FUSE) {
        // Write next layer's A-fragments directly (inverse of the
        // m16n8k16 lane map). cols c = 4l..4l+3 -> k-pairs p0 = 2l, p0+1.
        int tile = d >> 4, gg = d & 15;
        int side = gg >> 3, lrow = gg & 7;
        unsigned* fh = (unsigned*)g_xfh;
        unsigned* fl = (unsigned*)g_xfl;
        int p0 = 2 * l;
        int ks = p0 >> 3;
        int pp0 = p0 & 7, t0 = pp0 & 3, h0 = pp0 >> 2;
        int pp1 = pp0 + 1, t1 = pp1 & 3, h1 = pp1 >> 2;
        unsigned lw0, lw1;
        unsigned hw0 = pack_hi(o.x, o.y, lw0);
        unsigned hw1 = pack_hi(o.z, o.w, lw1);
        int base = (tile * 256 + ks * 32) * 4;
        int i0 = base + (lrow * 4 + t0) * 4 + h0 * 2 + side;
        int i1 = base + (lrow * 4 + t1) * 4 + h1 * 2 + side;
        fh[i0] = hw0; fl[i0] = lw0;
        fh[i1] = hw1; fl[i1] = lw1;
    } else {
        ((float4*)out)[d * ROWF4 + l] = o;
    }
}

// ---------------- Entry point ----------------
extern "C" void kernel_launch(void* const* d_in, const int* in_sizes, int n_in,
                              void* d_out, int out_size) {
    const float* x    = (const float*)d_in[0];
    const void*  ei   = d_in[1];
    const float* W1l  = (const float*)d_in[2];
    const float* W1r  = (const float*)d_in[3];
    const float* att1 = (const float*)d_in[4];
    const float* b1   = (const float*)d_in[5];
    const float* W2l  = (const float*)d_in[6];
    const float* W2r  = (const float*)d_in[7];
    const float* att2 = (const float*)d_in[8];
    const float* b2   = (const float*)d_in[9];
    const float* W3l  = (const float*)d_in[10];
    const float* W3r  = (const float*)d_in[11];
    const float* att3 = (const float*)d_in[12];
    const float* b3   = (const float*)d_in[13];
    float* out = (float*)d_out;

    float *d_xl, *d_xr;
    u64* d_wf;
    cudaGetSymbolAddress((void**)&d_xl, g_xl);
    cudaGetSymbolAddress((void**)&d_xr, g_xr);
    cudaGetSymbolAddress((void**)&d_wf, g_wf);

    // one-time preprocessing: dtype canon + CSR build + weight fragments
    prep_kernel<<<(NNODES + 255) / 256, 256>>>((const int*)ei);
    canon_hist_kernel<<<(ETOT + 255) / 256, 256>>>(ei);
    scan1_kernel<<<NBLK, 1024>>>();
    scan2_kernel<<<1, 32>>>();
    scan3_kernel<<<NBLK, 1024>>>();
    scatter_kernel<<<(ETOT + 255) / 256, 256>>>();
    convert_w_all_kernel<<<40, 256>>>(W1l, W1r, W2l, W2r, W3l, W3r);

    const dim3 ggrid((NT16 + 7) / 8, 2);
    const int ewarps128 = (NNODES * 32 + 255) / 256;        // warp per node
    const int ewarps64 = (NNODES / 2 * 32 + 255) / 256;     // 2 nodes per warp

    // Layer 1 (input x -> fragments -> gemm -> edge[fused convert])
    convert_x_kernel<<<(NT16 * 256 + 255) / 256, 256>>>(x);
    gemm_mma_kernel<128><<<ggrid, 256>>>(d_wf + WF_L1, d_xl, d_xr);
    csr_edge_kernel<32, true><<<ewarps128, 256>>>(att1, b1, nullptr);

    // Layer 2
    gemm_mma_kernel<128><<<ggrid, 256>>>(d_wf + WF_L2, d_xl, d_xr);
    csr_edge_kernel<32, true><<<ewarps128, 256>>>(att2, b2, nullptr);

    // Layer 3 (64 cols, plain fp32 output)
    gemm_mma_kernel<64><<<ggrid, 256>>>(d_wf + WF_L3, d_xl, d_xr);
    csr_edge_kernel<16, false><<<ewarps64, 256>>>(att3, b3, out);
}

// round 13
// speedup vs baseline: 1.0903x; 1.0903x over previous
#include <cuda_runtime.h>
#include <cuda_bf16.h>
#include <cstdint>

// ---------------- Problem constants ----------------
#define NNODES 50000
#define NEDGES 800000
#define ETOT   (NEDGES + NNODES)   // + self loops
#define NBLK   ((NNODES + 1023) / 1024)   // 49 scan blocks
#define NT16   (NNODES / 16)              // 3125 16-row fragment tiles (exact)

typedef unsigned long long u64;

// W fragment buffer layout (u64 units)
#define WF_L1 0
#define WF_L2 16384
#define WF_L3 32768

// ---------------- Device scratch (no allocs allowed) ----------------
__device__ float g_xl[NNODES * 128];
__device__ float g_xr[NNODES * 128];
__device__ uint4 g_xfh[NT16 * 8 * 32];   // A-fragments hi [tile16][ks][lane]
__device__ uint4 g_xfl[NT16 * 8 * 32];   // A-fragments lo
__device__ u64   g_wf[40960];            // all layers' W B-fragments
__device__ int   g_src[ETOT];
__device__ int   g_dst[ETOT];
__device__ int   g_csrc[ETOT];           // src ids sorted by dst (CSR)
__device__ int   g_rowptr[NNODES + 1];
__device__ int   g_deg[NNODES];
__device__ int   g_cnt[NNODES];
__device__ int   g_bsum[NBLK];
__device__ int   g_boff[NBLK];
__device__ int   g_is64;

// ---------------- mma.sync bf16 (sm_80+ PTX, family-wide) ----------------
__device__ __forceinline__ void mma_bf16(float* c, const uint4& a, u64 b) {
    unsigned b0 = (unsigned)b, b1 = (unsigned)(b >> 32);
    asm volatile(
        "mma.sync.aligned.m16n8k16.row.col.f32.bf16.bf16.f32 "
        "{%0,%1,%2,%3}, {%4,%5,%6,%7}, {%8,%9}, {%0,%1,%2,%3};"
        : "+f"(c[0]), "+f"(c[1]), "+f"(c[2]), "+f"(c[3])
        : "r"(a.x), "r"(a.y), "r"(a.z), "r"(a.w), "r"(b0), "r"(b1));
}

__device__ __forceinline__ unsigned pack_hi(float x, float y,
                                            unsigned& lo_out) {
    __nv_bfloat16 hx = __float2bfloat16_rn(x);
    __nv_bfloat16 hy = __float2bfloat16_rn(y);
    __nv_bfloat16 lx = __float2bfloat16_rn(x - __bfloat162float(hx));
    __nv_bfloat16 ly = __float2bfloat16_rn(y - __bfloat162float(hy));
    lo_out = ((unsigned)__bfloat16_as_ushort(ly) << 16) | __bfloat16_as_ushort(lx);
    return ((unsigned)__bfloat16_as_ushort(hy) << 16) | __bfloat16_as_ushort(hx);
}

// ---------------- zero counters + parallel dtype detect ----------------
__global__ void prep_kernel(const int* ei) {
    int i = blockIdx.x * blockDim.x + threadIdx.x;
    if (i < NNODES) { g_deg[i] = 0; g_cnt[i] = 0; }
    if (blockIdx.x == 0 && threadIdx.x < 32) {
        int nz = 0;
#pragma unroll
        for (int q = 0; q < 4; q++)
            nz |= ei[2 * (threadIdx.x * 4 + q) + 1];
        unsigned any = __ballot_sync(0xffffffffu, nz != 0);
        if (threadIdx.x == 0) g_is64 = (any == 0u);
    }
}

__global__ void canon_hist_kernel(const void* ei) {
    int i = blockIdx.x * blockDim.x + threadIdx.x;
    if (i >= ETOT) return;
    int s, d;
    if (i < NEDGES) {
        if (g_is64) {
            const long long* p = (const long long*)ei;
            s = (int)p[i];
            d = (int)p[NEDGES + i];
        } else {
            const int* p = (const int*)ei;
            s = p[i];
            d = p[NEDGES + i];
        }
    } else {
        s = d = i - NEDGES;
    }
    g_src[i] = s;
    g_dst[i] = d;
    atomicAdd(&g_deg[d], 1);
}

__global__ void scan1_kernel() {
    __shared__ int wtot[32];
    const int t = threadIdx.x, lane = t & 31, wid = t >> 5;
    const int gi = blockIdx.x * 1024 + t;
    int v = (gi < NNODES) ? g_deg[gi] : 0;
    int incl = v;
#pragma unroll
    for (int off = 1; off < 32; off <<= 1) {
        int x = __shfl_up_sync(0xffffffffu, incl, off);
        if (lane >= off) incl += x;
    }
    if (lane == 31) wtot[wid] = incl;
    __syncthreads();
    if (wid == 0) {
        int wv = wtot[lane];
        int wi = wv;
#pragma unroll
        for (int off = 1; off < 32; off <<= 1) {
            int x = __shfl_up_sync(0xffffffffu, wi, off);
            if (lane >= off) wi += x;
        }
        wtot[lane] = wi - wv;
    }
    __syncthreads();
    int excl = wtot[wid] + incl - v;
    if (gi < NNODES) g_rowptr[gi] = excl;
    if (t == 1023) g_bsum[blockIdx.x] = excl + v;
}

// parallel scan of the 49 block sums (64 threads, 2 warps)
__global__ void scan2_kernel() {
    __shared__ int wt[2];
    const int t = threadIdx.x, lane = t & 31, wid = t >> 5;
    int v = (t < NBLK) ? g_bsum[t] : 0;
    int incl = v;
#pragma unroll
    for (int off = 1; off < 32; off <<= 1) {
        int x = __shfl_up_sync(0xffffffffu, incl, off);
        if (lane >= off) incl += x;
    }
    if (lane == 31) wt[wid] = incl;
    __syncthreads();
    if (wid == 1) incl += wt[0];
    if (t < NBLK) g_boff[t] = incl - v;
    if (t == NBLK - 1) g_rowptr[NNODES] = incl;
}

__global__ void scan3_kernel() {
    int gi = blockIdx.x * 1024 + threadIdx.x;
    if (gi < NNODES && blockIdx.x > 0) g_rowptr[gi] += g_boff[blockIdx.x];
}

__global__ void scatter_kernel() {
    int i = blockIdx.x * blockDim.x + threadIdx.x;
    if (i >= ETOT) return;
    int d = g_dst[i];
    int pos = g_rowptr[d] + atomicAdd(&g_cnt[d], 1);
    g_csrc[pos] = g_src[i];
}

// ---------------- X -> A-fragment-major hi/lo conversion (layer 1 only) ----
__global__ void convert_x_kernel(const float* __restrict__ act) {
    int idx = blockIdx.x * blockDim.x + threadIdx.x;
    if (idx >= NT16 * 8 * 32) return;
    int lane = idx & 31;
    int ks = (idx >> 5) & 7;
    int tile = idx >> 8;
    int g = lane >> 2, t = lane & 3;
    int r0 = tile * 16 + g, r1 = r0 + 8;
    int c0 = (ks * 8 + t) * 2;
    int c1 = c0 + 8;

    float2 v0 = *(const float2*)&act[r0 * 128 + c0];
    float2 v1 = *(const float2*)&act[r1 * 128 + c0];
    float2 v2 = *(const float2*)&act[r0 * 128 + c1];
    float2 v3 = *(const float2*)&act[r1 * 128 + c1];

    uint4 hi, lo;
    hi.x = pack_hi(v0.x, v0.y, lo.x);
    hi.y = pack_hi(v1.x, v1.y, lo.y);
    hi.z = pack_hi(v2.x, v2.y, lo.z);
    hi.w = pack_hi(v3.x, v3.y, lo.w);
    g_xfh[idx] = hi;
    g_xfl[idx] = lo;
}

// ---------------- All-layer W -> B-fragment conversion (one kernel) --------
__device__ __forceinline__ void convert_w_one(u64* base, const float* Wl,
                                              const float* Wr, int local,
                                              int COLS, int NT, int PART) {
    int lane = local & 31;
    int nt = (local >> 5) % NT;
    int ks = (local >> 5) / NT;
    int g = lane >> 2, t = lane & 3;
    int n = nt * 8 + g;
    int k0 = (ks * 8 + t) * 2;
    int k1 = k0 + 8;

    unsigned lo0, lo1;
    unsigned hi0 = pack_hi(Wl[k0 * COLS + n], Wl[(k0 + 1) * COLS + n], lo0);
    unsigned hi1 = pack_hi(Wl[k1 * COLS + n], Wl[(k1 + 1) * COLS + n], lo1);
    base[0 * PART + local] = ((u64)hi1 << 32) | hi0;
    base[1 * PART + local] = ((u64)lo1 << 32) | lo0;

    hi0 = pack_hi(Wr[k0 * COLS + n], Wr[(k0 + 1) * COLS + n], lo0);
    hi1 = pack_hi(Wr[k1 * COLS + n], Wr[(k1 + 1) * COLS + n], lo1);
    base[2 * PART + local] = ((u64)hi1 << 32) | hi0;
    base[3 * PART + local] = ((u64)lo1 << 32) | lo0;
}

__global__ void convert_w_all_kernel(const float* W1l, const float* W1r,
                                     const float* W2l, const float* W2r,
                                     const float* W3l, const float* W3r) {
    int idx = blockIdx.x * blockDim.x + threadIdx.x;
    if (idx < 4096) {
        convert_w_one(g_wf + WF_L1, W1l, W1r, idx, 128, 16, 4096);
    } else if (idx < 8192) {
        convert_w_one(g_wf + WF_L2, W2l, W2r, idx - 4096, 128, 16, 4096);
    } else if (idx < 10240) {
        convert_w_one(g_wf + WF_L3, W3l, W3r, idx - 8192, 64, 8, 2048);
    }
}

// ---------------- HMMA dual GEMM (R11-proven shape) ----------------
// 3xBF16 split: D = Xhi@Whi + Xhi@Wlo + Xlo@Whi, fp32 accumulate.
// CTA = 8 warps: warp w -> matrix (w>>2), 16-row tile blockIdx*4 + (w&3).
template <int COLS>
__global__ __launch_bounds__(256) void gemm_mma_kernel(const u64* __restrict__ wf,
                                                       float* __restrict__ Yl,
                                                       float* __restrict__ Yr) {
    constexpr int NT = COLS / 8;
    constexpr int PART = 8 * NT * 32;
    const int tid = threadIdx.x;
    const int w = tid >> 5, lane = tid & 31;
    const int mat = w >> 2;
    const int tile = blockIdx.x * 4 + (w & 3);
    if (tile >= NT16) return;
    const int g = lane >> 2, t = lane & 3;

    const u64* Wh = wf + mat * 2 * PART;
    const u64* Wlo = Wh + PART;
    const uint4* Ah = g_xfh + tile * 256;
    const uint4* Al = g_xfl + tile * 256;

    float acc[NT][4];
#pragma unroll
    for (int nt = 0; nt < NT; nt++)
#pragma unroll
        for (int j = 0; j < 4; j++) acc[nt][j] = 0.0f;

#pragma unroll
    for (int ks = 0; ks < 8; ks++) {
        uint4 ahi = Ah[ks * 32 + lane];
        uint4 alo = Al[ks * 32 + lane];
        const u64* whk = Wh + (ks * NT) * 32 + lane;
        const u64* wlk = Wlo + (ks * NT) * 32 + lane;
#pragma unroll
        for (int nt = 0; nt < NT; nt++) {
            u64 bh = whk[nt * 32];
            u64 bl = wlk[nt * 32];
            mma_bf16(acc[nt], ahi, bh);
            mma_bf16(acc[nt], ahi, bl);
            mma_bf16(acc[nt], alo, bh);
        }
    }

    float* Y = mat ? Yr : Yl;
    const int r0 = tile * 16 + g, r1 = r0 + 8;
#pragma unroll
    for (int nt = 0; nt < NT; nt++) {
        int c = nt * 8 + t * 2;
        *(float2*)&Y[r0 * COLS + c] = make_float2(acc[nt][0], acc[nt][1]);
        *(float2*)&Y[r1 * COLS + c] = make_float2(acc[nt][2], acc[nt][3]);
    }
}

// ---------------- shared edge math (one node, ROWF4=32) ----------------
__device__ __forceinline__ float4 edge_node_128(int d, const float* att,
                                                const float* bias, int l) {
    const float4* xl4 = (const float4*)g_xl;
    float4 b = ((const float4*)g_xr)[d * 32 + l];
    float4 w = ((const float4*)att)[l];

    float4 acc = make_float4(0.f, 0.f, 0.f, 0.f);
    float den = 0.f;

    int i = g_rowptr[d];
    const int end = g_rowptr[d + 1];

    int s0 = g_csrc[i];
    int s1 = (i + 1 < end) ? g_csrc[i + 1] : 0;
    float4 a0 = xl4[s0 * 32 + l];
    float4 a1 = xl4[s1 * 32 + l];

    while (i < end) {
        const int ni = i + 2;
        int t0 = (ni < end) ? g_csrc[ni] : 0;
        int t1 = (ni + 1 < end) ? g_csrc[ni + 1] : 0;
        float4 n0 = xl4[t0 * 32 + l];
        float4 n1 = xl4[t1 * 32 + l];

        float vx0 = a0.x + b.x, vy0 = a0.y + b.y, vz0 = a0.z + b.z, vw0 = a0.w + b.w;
        float vx1 = a1.x + b.x, vy1 = a1.y + b.y, vz1 = a1.z + b.z, vw1 = a1.w + b.w;
        vx0 = vx0 > 0.f ? vx0 : 0.2f * vx0;  vx1 = vx1 > 0.f ? vx1 : 0.2f * vx1;
        vy0 = vy0 > 0.f ? vy0 : 0.2f * vy0;  vy1 = vy1 > 0.f ? vy1 : 0.2f * vy1;
        vz0 = vz0 > 0.f ? vz0 : 0.2f * vz0;  vz1 = vz1 > 0.f ? vz1 : 0.2f * vz1;
        vw0 = vw0 > 0.f ? vw0 : 0.2f * vw0;  vw1 = vw1 > 0.f ? vw1 : 0.2f * vw1;
        float p0 = vx0 * w.x + vy0 * w.y + vz0 * w.z + vw0 * w.w;
        float p1 = vx1 * w.x + vy1 * w.y + vz1 * w.z + vw1 * w.w;

        p0 += __shfl_xor_sync(0xffffffffu, p0, 8);
        p1 += __shfl_xor_sync(0xffffffffu, p1, 8);
        p0 += __shfl_xor_sync(0xffffffffu, p0, 4);
        p1 += __shfl_xor_sync(0xffffffffu, p1, 4);
        p0 += __shfl_xor_sync(0xffffffffu, p0, 2);
        p1 += __shfl_xor_sync(0xffffffffu, p1, 2);
        p0 += __shfl_xor_sync(0xffffffffu, p0, 1);
        p1 += __shfl_xor_sync(0xffffffffu, p1, 1);

        float ex0 = __expf(p0);
        float ex1 = (i + 1 < end) ? __expf(p1) : 0.f;

        acc.x += ex0 * a0.x + ex1 * a1.x;
        acc.y += ex0 * a0.y + ex1 * a1.y;
        acc.z += ex0 * a0.z + ex1 * a1.z;
        acc.w += ex0 * a0.w + ex1 * a1.w;
        den += ex0 + ex1;

        a0 = n0; a1 = n1;
        i = ni;
    }

    float4 bi = ((const float4*)bias)[l];
    float inv = 1.0f / den;
    float4 o;
    o.x = acc.x * inv + bi.x;
    o.y = acc.y * inv + bi.y;
    o.z = acc.z * inv + bi.z;
    o.w = acc.w * inv + bi.w;
    o.x = o.x > 0.f ? o.x : (__expf(o.x) - 1.f);
    o.y = o.y > 0.f ? o.y : (__expf(o.y) - 1.f);
    o.z = o.z > 0.f ? o.z : (__expf(o.z) - 1.f);
    o.w = o.w > 0.f ? o.w : (__expf(o.w) - 1.f);
    return o;
}

// ---------------- Fused edge pass (layers 1-2): 512 thr = 16 nodes = 1 tile
// Stages ELU output in smem, then writes next layer's A-fragments coalesced.
__global__ __launch_bounds__(512) void csr_edge_fused_kernel(
        const float* __restrict__ att, const float* __restrict__ bias) {
    __shared__ float s[16 * 132];       // padded rows: bank-conflict-free
    const int tid = threadIdx.x;
    const int w = tid >> 5, l = tid & 31;
    const int tile = blockIdx.x;
    const int d = tile * 16 + w;        // NNODES = NT16*16 exactly

    float4 o = edge_node_128(d, att, bias, l);
    *(float4*)&s[w * 132 + 4 * l] = o;
    __syncthreads();

    if (tid < 256) {
        int lane = tid & 31;
        int ks = tid >> 5;
        int g = lane >> 2, t = lane & 3;
        int c0 = (ks * 8 + t) * 2;
        int c1 = c0 + 8;
        const float* r0 = &s[g * 132];
        const float* r1 = &s[(g + 8) * 132];
        uint4 hi, lo;
        hi.x = pack_hi(r0[c0], r0[c0 + 1], lo.x);
        hi.y = pack_hi(r1[c0], r1[c0 + 1], lo.y);
        hi.z = pack_hi(r0[c1], r0[c1 + 1], lo.z);
        hi.w = pack_hi(r1[c1], r1[c1 + 1], lo.w);
        int idx = tile * 256 + ks * 32 + lane;
        g_xfh[idx] = hi;
        g_xfl[idx] = lo;
    }
}

// ---------------- Final edge pass (layer 3, 64 ch, fp32 out) ----------------
__global__ void csr_edge64_kernel(const float* __restrict__ att,
                                  const float* __restrict__ bias,
                                  float* __restrict__ out) {
    int gwarp = (blockIdx.x * blockDim.x + threadIdx.x) >> 5;
    int lane = threadIdx.x & 31;
    int sub = lane >> 4;
    int l = lane & 15;
    int d = gwarp * 2 + sub;
    if (d >= NNODES) return;

    const float4* xl4 = (const float4*)g_xl;
    float4 b = ((const float4*)g_xr)[d * 16 + l];
    float4 w = ((const float4*)att)[l];

    float4 acc = make_float4(0.f, 0.f, 0.f, 0.f);
    float den = 0.f;

    int i = g_rowptr[d];
    const int end = g_rowptr[d + 1];

    int s0 = g_csrc[i];
    int s1 = (i + 1 < end) ? g_csrc[i + 1] : 0;
    float4 a0 = xl4[s0 * 16 + l];
    float4 a1 = xl4[s1 * 16 + l];

    while (i < end) {
        const int ni = i + 2;
        int t0 = (ni < end) ? g_csrc[ni] : 0;
        int t1 = (ni + 1 < end) ? g_csrc[ni + 1] : 0;
        float4 n0 = xl4[t0 * 16 + l];
        float4 n1 = xl4[t1 * 16 + l];

        float vx0 = a0.x + b.x, vy0 = a0.y + b.y, vz0 = a0.z + b.z, vw0 = a0.w + b.w;
        float vx1 = a1.x + b.x, vy1 = a1.y + b.y, vz1 = a1.z + b.z, vw1 = a1.w + b.w;
        vx0 = vx0 > 0.f ? vx0 : 0.2f * vx0;  vx1 = vx1 > 0.f ? vx1 : 0.2f * vx1;
        vy0 = vy0 > 0.f ? vy0 : 0.2f * vy0;  vy1 = vy1 > 0.f ? vy1 : 0.2f * vy1;
        vz0 = vz0 > 0.f ? vz0 : 0.2f * vz0;  vz1 = vz1 > 0.f ? vz1 : 0.2f * vz1;
        vw0 = vw0 > 0.f ? vw0 : 0.2f * vw0;  vw1 = vw1 > 0.f ? vw1 : 0.2f * vw1;
        float p0 = vx0 * w.x + vy0 * w.y + vz0 * w.z + vw0 * w.w;
        float p1 = vx1 * w.x + vy1 * w.y + vz1 * w.z + vw1 * w.w;

        p0 += __shfl_xor_sync(0xffffffffu, p0, 8);
        p1 += __shfl_xor_sync(0xffffffffu, p1, 8);
        p0 += __shfl_xor_sync(0xffffffffu, p0, 4);
        p1 += __shfl_xor_sync(0xffffffffu, p1, 4);
        p0 += __shfl_xor_sync(0xffffffffu, p0, 2);
        p1 += __shfl_xor_sync(0xffffffffu, p1, 2);
        p0 += __shfl_xor_sync(0xffffffffu, p0, 1);
        p1 += __shfl_xor_sync(0xffffffffu, p1, 1);

        float ex0 = __expf(p0);
        float ex1 = (i + 1 < end) ? __expf(p1) : 0.f;

        acc.x += ex0 * a0.x + ex1 * a1.x;
        acc.y += ex0 * a0.y + ex1 * a1.y;
        acc.z += ex0 * a0.z + ex1 * a1.z;
        acc.w += ex0 * a0.w + ex1 * a1.w;
        den += ex0 + ex1;

        a0 = n0; a1 = n1;
        i = ni;
    }

    float4 bi = ((const float4*)bias)[l];
    float inv = 1.0f / den;
    float4 o;
    o.x = acc.x * inv + bi.x;
    o.y = acc.y * inv + bi.y;
    o.z = acc.z * inv + bi.z;
    o.w = acc.w * inv + bi.w;
    o.x = o.x > 0.f ? o.x : (__expf(o.x) - 1.f);
    o.y = o.y > 0.f ? o.y : (__expf(o.y) - 1.f);
    o.z = o.z > 0.f ? o.z : (__expf(o.z) - 1.f);
    o.w = o.w > 0.f ? o.w : (__expf(o.w) - 1.f);
    ((float4*)out)[d * 16 + l] = o;
}

// ---------------- Entry point ----------------
extern "C" void kernel_launch(void* const* d_in, const int* in_sizes, int n_in,
                              void* d_out, int out_size) {
    const float* x    = (const float*)d_in[0];
    const void*  ei   = d_in[1];
    const float* W1l  = (const float*)d_in[2];
    const float* W1r  = (const float*)d_in[3];
    const float* att1 = (const float*)d_in[4];
    const float* b1   = (const float*)d_in[5];
    const float* W2l  = (const float*)d_in[6];
    const float* W2r  = (const float*)d_in[7];
    const float* att2 = (const float*)d_in[8];
    const float* b2   = (const float*)d_in[9];
    const float* W3l  = (const float*)d_in[10];
    const float* W3r  = (const float*)d_in[11];
    const float* att3 = (const float*)d_in[12];
    const float* b3   = (const float*)d_in[13];
    float* out = (float*)d_out;

    float *d_xl, *d_xr;
    u64* d_wf;
    cudaGetSymbolAddress((void**)&d_xl, g_xl);
    cudaGetSymbolAddress((void**)&d_xr, g_xr);
    cudaGetSymbolAddress((void**)&d_wf, g_wf);

    // one-time preprocessing: dtype canon + CSR build + weight fragments
    prep_kernel<<<(NNODES + 255) / 256, 256>>>((const int*)ei);
    canon_hist_kernel<<<(ETOT + 255) / 256, 256>>>(ei);
    scan1_kernel<<<NBLK, 1024>>>();
    scan2_kernel<<<1, 64>>>();
    scan3_kernel<<<NBLK, 1024>>>();
    scatter_kernel<<<(ETOT + 255) / 256, 256>>>();
    convert_w_all_kernel<<<40, 256>>>(W1l, W1r, W2l, W2r, W3l, W3r);

    const int ggrid = (NT16 + 3) / 4;
    const int ewarps64 = (NNODES / 2 * 32 + 255) / 256;

    // Layer 1
    convert_x_kernel<<<(NT16 * 256 + 255) / 256, 256>>>(x);
    gemm_mma_kernel<128><<<ggrid, 256>>>(d_wf + WF_L1, d_xl, d_xr);
    csr_edge_fused_kernel<<<NT16, 512>>>(att1, b1);

    // Layer 2
    gemm_mma_kernel<128><<<ggrid, 256>>>(d_wf + WF_L2, d_xl, d_xr);
    csr_edge_fused_kernel<<<NT16, 512>>>(att2, b2);

    // Layer 3 (64 cols, plain fp32 output)
    gemm_mma_kernel<64><<<ggrid, 256>>>(d_wf + WF_L3, d_xl, d_xr);
    csr_edge64_kernel<<<ewarps64, 256>>>(att3, b3, out);
}

// round 15
// speedup vs baseline: 1.1276x; 1.0342x over previous
#include <cuda_runtime.h>
#include <cuda_bf16.h>
#include <cstdint>

// ---------------- Problem constants ----------------
#define NNODES 50000
#define NEDGES 800000
#define ETOT   (NEDGES + NNODES)   // + self loops
#define NBLK   ((NNODES + 1023) / 1024)   // 49 scan blocks
#define NT16   (NNODES / 16)              // 3125 16-row fragment tiles (exact)

typedef unsigned long long u64;

// W fragment buffer layout (u64 units)
#define WF_L1 0
#define WF_L2 16384
#define WF_L3 32768

// ---------------- Device scratch (no allocs allowed) ----------------
__device__ float g_xl[NNODES * 128];
__device__ float g_xr[NNODES * 128];
__device__ float g_h[NNODES * 128];      // layer activation ping buffer (fp32)
__device__ u64   g_wf[40960];            // all layers' W B-fragments
__device__ int   g_src[ETOT];
__device__ int   g_dst[ETOT];
__device__ int   g_csrc[ETOT];           // src ids sorted by dst (CSR)
__device__ int   g_rowptr[NNODES + 1];
__device__ int   g_deg[NNODES];
__device__ int   g_cnt[NNODES];
__device__ int   g_bsum[NBLK];
__device__ int   g_boff[NBLK];
__device__ int   g_is64;

// ---------------- mma.sync bf16 (sm_80+ PTX, family-wide) ----------------
__device__ __forceinline__ void mma_bf16(float* c, const uint4& a, u64 b) {
    unsigned b0 = (unsigned)b, b1 = (unsigned)(b >> 32);
    asm volatile(
        "mma.sync.aligned.m16n8k16.row.col.f32.bf16.bf16.f32 "
        "{%0,%1,%2,%3}, {%4,%5,%6,%7}, {%8,%9}, {%0,%1,%2,%3};"
        : "+f"(c[0]), "+f"(c[1]), "+f"(c[2]), "+f"(c[3])
        : "r"(a.x), "r"(a.y), "r"(a.z), "r"(a.w), "r"(b0), "r"(b1));
}

__device__ __forceinline__ unsigned pack_hi(float x, float y,
                                            unsigned& lo_out) {
    __nv_bfloat16 hx = __float2bfloat16_rn(x);
    __nv_bfloat16 hy = __float2bfloat16_rn(y);
    __nv_bfloat16 lx = __float2bfloat16_rn(x - __bfloat162float(hx));
    __nv_bfloat16 ly = __float2bfloat16_rn(y - __bfloat162float(hy));
    lo_out = ((unsigned)__bfloat16_as_ushort(ly) << 16) | __bfloat16_as_ushort(lx);
    return ((unsigned)__bfloat16_as_ushort(hy) << 16) | __bfloat16_as_ushort(hx);
}

// ---------------- zero counters + parallel dtype detect ----------------
__global__ void prep_kernel(const int* ei) {
    int i = blockIdx.x * blockDim.x + threadIdx.x;
    if (i < NNODES) { g_deg[i] = 0; g_cnt[i] = 0; }
    if (blockIdx.x == 0 && threadIdx.x < 32) {
        int nz = 0;
#pragma unroll
        for (int q = 0; q < 4; q++)
            nz |= ei[2 * (threadIdx.x * 4 + q) + 1];
        unsigned any = __ballot_sync(0xffffffffu, nz != 0);
        if (threadIdx.x == 0) g_is64 = (any == 0u);
    }
}

__global__ void canon_hist_kernel(const void* ei) {
    int i = blockIdx.x * blockDim.x + threadIdx.x;
    if (i >= ETOT) return;
    int s, d;
    if (i < NEDGES) {
        if (g_is64) {
            const long long* p = (const long long*)ei;
            s = (int)p[i];
            d = (int)p[NEDGES + i];
        } else {
            const int* p = (const int*)ei;
            s = p[i];
            d = p[NEDGES + i];
        }
    } else {
        s = d = i - NEDGES;
    }
    g_src[i] = s;
    g_dst[i] = d;
    atomicAdd(&g_deg[d], 1);
}

__global__ void scan1_kernel() {
    __shared__ int wtot[32];
    const int t = threadIdx.x, lane = t & 31, wid = t >> 5;
    const int gi = blockIdx.x * 1024 + t;
    int v = (gi < NNODES) ? g_deg[gi] : 0;
    int incl = v;
#pragma unroll
    for (int off = 1; off < 32; off <<= 1) {
        int x = __shfl_up_sync(0xffffffffu, incl, off);
        if (lane >= off) incl += x;
    }
    if (lane == 31) wtot[wid] = incl;
    __syncthreads();
    if (wid == 0) {
        int wv = wtot[lane];
        int wi = wv;
#pragma unroll
        for (int off = 1; off < 32; off <<= 1) {
            int x = __shfl_up_sync(0xffffffffu, wi, off);
            if (lane >= off) wi += x;
        }
        wtot[lane] = wi - wv;
    }
    __syncthreads();
    int excl = wtot[wid] + incl - v;
    if (gi < NNODES) g_rowptr[gi] = excl;
    if (t == 1023) g_bsum[blockIdx.x] = excl + v;
}

// parallel scan of the 49 block sums (64 threads, 2 warps)
__global__ void scan2_kernel() {
    __shared__ int wt[2];
    const int t = threadIdx.x, lane = t & 31, wid = t >> 5;
    int v = (t < NBLK) ? g_bsum[t] : 0;
    int incl = v;
#pragma unroll
    for (int off = 1; off < 32; off <<= 1) {
        int x = __shfl_up_sync(0xffffffffu, incl, off);
        if (lane >= off) incl += x;
    }
    if (lane == 31) wt[wid] = incl;
    __syncthreads();
    if (wid == 1) incl += wt[0];
    if (t < NBLK) g_boff[t] = incl - v;
    if (t == NBLK - 1) g_rowptr[NNODES] = incl;
}

__global__ void scan3_kernel() {
    int gi = blockIdx.x * 1024 + threadIdx.x;
    if (gi < NNODES && blockIdx.x > 0) g_rowptr[gi] += g_boff[blockIdx.x];
}

__global__ void scatter_kernel() {
    int i = blockIdx.x * blockDim.x + threadIdx.x;
    if (i >= ETOT) return;
    int d = g_dst[i];
    int pos = g_rowptr[d] + atomicAdd(&g_cnt[d], 1);
    g_csrc[pos] = g_src[i];
}

// ---------------- All-layer W -> B-fragment conversion (one kernel) --------
__device__ __forceinline__ void convert_w_one(u64* base, const float* Wl,
                                              const float* Wr, int local,
                                              int COLS, int NT, int PART) {
    int lane = local & 31;
    int nt = (local >> 5) % NT;
    int ks = (local >> 5) / NT;
    int g = lane >> 2, t = lane & 3;
    int n = nt * 8 + g;
    int k0 = (ks * 8 + t) * 2;
    int k1 = k0 + 8;

    unsigned lo0, lo1;
    unsigned hi0 = pack_hi(Wl[k0 * COLS + n], Wl[(k0 + 1) * COLS + n], lo0);
    unsigned hi1 = pack_hi(Wl[k1 * COLS + n], Wl[(k1 + 1) * COLS + n], lo1);
    base[0 * PART + local] = ((u64)hi1 << 32) | hi0;
    base[1 * PART + local] = ((u64)lo1 << 32) | lo0;

    hi0 = pack_hi(Wr[k0 * COLS + n], Wr[(k0 + 1) * COLS + n], lo0);
    hi1 = pack_hi(Wr[k1 * COLS + n], Wr[(k1 + 1) * COLS + n], lo1);
    base[2 * PART + local] = ((u64)hi1 << 32) | hi0;
    base[3 * PART + local] = ((u64)lo1 << 32) | lo0;
}

__global__ void convert_w_all_kernel(const float* W1l, const float* W1r,
                                     const float* W2l, const float* W2r,
                                     const float* W3l, const float* W3r) {
    int idx = blockIdx.x * blockDim.x + threadIdx.x;
    if (idx < 4096) {
        convert_w_one(g_wf + WF_L1, W1l, W1r, idx, 128, 16, 4096);
    } else if (idx < 8192) {
        convert_w_one(g_wf + WF_L2, W2l, W2r, idx - 4096, 128, 16, 4096);
    } else if (idx < 10240) {
        convert_w_one(g_wf + WF_L3, W3l, W3r, idx - 8192, 64, 8, 2048);
    }
}

// ---------------- HMMA dual GEMM with inline fp32 -> split-bf16 A ----------
// 3xBF16 split: D = Xhi@Whi + Xhi@Wlo + Xlo@Whi, fp32 accumulate.
// A is read as fp32 rows of Xin [N,128] and packed on the fly (identical
// math to the old convert_x kernel, relocated).
// CTA = 8 warps: warp w -> matrix (w>>2), 16-row tile blockIdx*4 + (w&3).
template <int COLS>
__global__ __launch_bounds__(256) void gemm_mma_kernel(
        const float* __restrict__ Xin, const u64* __restrict__ wf,
        float* __restrict__ Yl, float* __restrict__ Yr) {
    constexpr int NT = COLS / 8;
    constexpr int PART = 8 * NT * 32;
    const int tid = threadIdx.x;
    const int w = tid >> 5, lane = tid & 31;
    const int mat = w >> 2;
    const int tile = blockIdx.x * 4 + (w & 3);
    if (tile >= NT16) return;
    const int g = lane >> 2, t = lane & 3;

    const u64* Wh = wf + mat * 2 * PART;
    const u64* Wlo = Wh + PART;
    const float* X0 = Xin + (tile * 16 + g) * 128;      // row r0
    const float* X1 = X0 + 8 * 128;                     // row r1

    float acc[NT][4];
#pragma unroll
    for (int nt = 0; nt < NT; nt++)
#pragma unroll
        for (int j = 0; j < 4; j++) acc[nt][j] = 0.0f;

#pragma unroll
    for (int ks = 0; ks < 8; ks++) {
        const int c0 = ks * 16 + 2 * t;
        const int c1 = c0 + 8;
        float2 v0 = *(const float2*)&X0[c0];
        float2 v1 = *(const float2*)&X1[c0];
        float2 v2 = *(const float2*)&X0[c1];
        float2 v3 = *(const float2*)&X1[c1];
        uint4 ahi, alo;
        ahi.x = pack_hi(v0.x, v0.y, alo.x);
        ahi.y = pack_hi(v1.x, v1.y, alo.y);
        ahi.z = pack_hi(v2.x, v2.y, alo.z);
        ahi.w = pack_hi(v3.x, v3.y, alo.w);

        const u64* whk = Wh + (ks * NT) * 32 + lane;
        const u64* wlk = Wlo + (ks * NT) * 32 + lane;
#pragma unroll
        for (int nt = 0; nt < NT; nt++) {
            u64 bh = whk[nt * 32];
            u64 bl = wlk[nt * 32];
            mma_bf16(acc[nt], ahi, bh);
            mma_bf16(acc[nt], ahi, bl);
            mma_bf16(acc[nt], alo, bh);
        }
    }

    float* Y = mat ? Yr : Yl;
    const int r0 = tile * 16 + g, r1 = r0 + 8;
#pragma unroll
    for (int nt = 0; nt < NT; nt++) {
        int c = nt * 8 + t * 2;
        *(float2*)&Y[r0 * COLS + c] = make_float2(acc[nt][0], acc[nt][1]);
        *(float2*)&Y[r1 * COLS + c] = make_float2(acc[nt][2], acc[nt][3]);
    }
}

// ---------------- CSR edge pass (R11-proven): 2-edge pipelined -------------
template <int ROWF4>
__global__ void csr_edge_kernel(const float* __restrict__ att,
                                const float* __restrict__ bias,
                                float* __restrict__ out) {
    constexpr int NPW = 32 / ROWF4;
    int gwarp = (blockIdx.x * blockDim.x + threadIdx.x) >> 5;
    int lane = threadIdx.x & 31;
    int sub = lane / ROWF4;
    int l = lane % ROWF4;
    int d = gwarp * NPW + sub;
    if (d >= NNODES) return;

    const float4* xl4 = (const float4*)g_xl;
    float4 b = ((const float4*)g_xr)[d * ROWF4 + l];
    float4 w = ((const float4*)att)[l];

    float4 acc = make_float4(0.f, 0.f, 0.f, 0.f);
    float den = 0.f;

    int i = g_rowptr[d];
    const int end = g_rowptr[d + 1];

    int s0 = g_csrc[i];
    int s1 = (i + 1 < end) ? g_csrc[i + 1] : 0;
    float4 a0 = xl4[s0 * ROWF4 + l];
    float4 a1 = xl4[s1 * ROWF4 + l];

    while (i < end) {
        const int ni = i + 2;
        int t0 = (ni < end) ? g_csrc[ni] : 0;
        int t1 = (ni + 1 < end) ? g_csrc[ni + 1] : 0;
        float4 n0 = xl4[t0 * ROWF4 + l];
        float4 n1 = xl4[t1 * ROWF4 + l];

        float vx0 = a0.x + b.x, vy0 = a0.y + b.y, vz0 = a0.z + b.z, vw0 = a0.w + b.w;
        float vx1 = a1.x + b.x, vy1 = a1.y + b.y, vz1 = a1.z + b.z, vw1 = a1.w + b.w;
        vx0 = vx0 > 0.f ? vx0 : 0.2f * vx0;  vx1 = vx1 > 0.f ? vx1 : 0.2f * vx1;
        vy0 = vy0 > 0.f ? vy0 : 0.2f * vy0;  vy1 = vy1 > 0.f ? vy1 : 0.2f * vy1;
        vz0 = vz0 > 0.f ? vz0 : 0.2f * vz0;  vz1 = vz1 > 0.f ? vz1 : 0.2f * vz1;
        vw0 = vw0 > 0.f ? vw0 : 0.2f * vw0;  vw1 = vw1 > 0.f ? vw1 : 0.2f * vw1;
        float p0 = vx0 * w.x + vy0 * w.y + vz0 * w.z + vw0 * w.w;
        float p1 = vx1 * w.x + vy1 * w.y + vz1 * w.z + vw1 * w.w;

        p0 += __shfl_xor_sync(0xffffffffu, p0, 8);
        p1 += __shfl_xor_sync(0xffffffffu, p1, 8);
        p0 += __shfl_xor_sync(0xffffffffu, p0, 4);
        p1 += __shfl_xor_sync(0xffffffffu, p1, 4);
        p0 += __shfl_xor_sync(0xffffffffu, p0, 2);
        p1 += __shfl_xor_sync(0xffffffffu, p1, 2);
        p0 += __shfl_xor_sync(0xffffffffu, p0, 1);
        p1 += __shfl_xor_sync(0xffffffffu, p1, 1);

        float ex0 = __expf(p0);
        float ex1 = (i + 1 < end) ? __expf(p1) : 0.f;

        acc.x += ex0 * a0.x + ex1 * a1.x;
        acc.y += ex0 * a0.y + ex1 * a1.y;
        acc.z += ex0 * a0.z + ex1 * a1.z;
        acc.w += ex0 * a0.w + ex1 * a1.w;
        den += ex0 + ex1;

        a0 = n0; a1 = n1;
        i = ni;
    }

    float4 bi = ((const float4*)bias)[l];
    float inv = 1.0f / den;
    float4 o;
    o.x = acc.x * inv + bi.x;
    o.y = acc.y * inv + bi.y;
    o.z = acc.z * inv + bi.z;
    o.w = acc.w * inv + bi.w;
    o.x = o.x > 0.f ? o.x : (__expf(o.x) - 1.f);
    o.y = o.y > 0.f ? o.y : (__expf(o.y) - 1.f);
    o.z = o.z > 0.f ? o.z : (__expf(o.z) - 1.f);
    o.w = o.w > 0.f ? o.w : (__expf(o.w) - 1.f);
    ((float4*)out)[d * ROWF4 + l] = o;
}

// ---------------- Entry point ----------------
extern "C" void kernel_launch(void* const* d_in, const int* in_sizes, int n_in,
                              void* d_out, int out_size) {
    const float* x    = (const float*)d_in[0];
    const void*  ei   = d_in[1];
    const float* W1l  = (const float*)d_in[2];
    const float* W1r  = (const float*)d_in[3];
    const float* att1 = (const float*)d_in[4];
    const float* b1   = (const float*)d_in[5];
    const float* W2l  = (const float*)d_in[6];
    const float* W2r  = (const float*)d_in[7];
    const float* att2 = (const float*)d_in[8];
    const float* b2   = (const float*)d_in[9];
    const float* W3l  = (const float*)d_in[10];
    const float* W3r  = (const float*)d_in[11];
    const float* att3 = (const float*)d_in[12];
    const float* b3   = (const float*)d_in[13];
    float* out = (float*)d_out;

    float *d_xl, *d_xr, *d_h;
    u64* d_wf;
    cudaGetSymbolAddress((void**)&d_xl, g_xl);
    cudaGetSymbolAddress((void**)&d_xr, g_xr);
    cudaGetSymbolAddress((void**)&d_h,  g_h);
    cudaGetSymbolAddress((void**)&d_wf, g_wf);

    // one-time preprocessing: dtype canon + CSR build + weight fragments
    prep_kernel<<<(NNODES + 255) / 256, 256>>>((const int*)ei);
    canon_hist_kernel<<<(ETOT + 255) / 256, 256>>>(ei);
    scan1_kernel<<<NBLK, 1024>>>();
    scan2_kernel<<<1, 64>>>();
    scan3_kernel<<<NBLK, 1024>>>();
    scatter_kernel<<<(ETOT + 255) / 256, 256>>>();
    convert_w_all_kernel<<<40, 256>>>(W1l, W1r, W2l, W2r, W3l, W3r);

    const int ggrid = (NT16 + 3) / 4;
    const int ewarps128 = (NNODES * 32 + 255) / 256;     // warp per node
    const int ewarps64 = (NNODES / 2 * 32 + 255) / 256;  // 2 nodes per warp

    // Layer 1
    gemm_mma_kernel<128><<<ggrid, 256>>>(x, d_wf + WF_L1, d_xl, d_xr);
    csr_edge_kernel<32><<<ewarps128, 256>>>(att1, b1, d_h);

    // Layer 2
    gemm_mma_kernel<128><<<ggrid, 256>>>(d_h, d_wf + WF_L2, d_xl, d_xr);
    csr_edge_kernel<32><<<ewarps128, 256>>>(att2, b2, d_h);

    // Layer 3 (64 cols, fp32 output)
    gemm_mma_kernel<64><<<ggrid, 256>>>(d_h, d_wf + WF_L3, d_xl, d_xr);
    csr_edge_kernel<16><<<ewarps64, 256>>>(att3, b3, out);
}